// round 5
// baseline (speedup 1.0000x reference)
#include <cuda_runtime.h>
#include <cuda_bf16.h>
#include <cstdint>

// Problem constants (fixed shapes from reference)
#define NE   16          // experts
#define KTOP 2           // top-k
#define DIM  1024        // model dim
#define FF   512         // ffn dim
#define NT   4096        // tokens
#define CAP  2048        // per-expert capacity
#define TKS  (NT*KTOP)   // total slots

// ---- device scratch (allocation-free rule: __device__ globals) ----
__device__ int   g_counts[NE];
__device__ int   g_tok[NE*CAP];          // token id per (expert, pos)
__device__ float g_wgt[NE*CAP];          // routing weight per (expert, pos)
__device__ float g_h[(size_t)NE*CAP*FF]; // intermediate h, 64 MB

// ------------------------------------------------------------------
// Zero output + counters (vectorized)
// ------------------------------------------------------------------
__global__ void k_zero(float4* __restrict__ out4) {
    int i = blockIdx.x * blockDim.x + threadIdx.x;
    if (i < NE) g_counts[i] = 0;
    const float4 z = make_float4(0.f, 0.f, 0.f, 0.f);
    for (int j = i; j < NT * DIM / 4; j += gridDim.x * blockDim.x) out4[j] = z;
}

// ------------------------------------------------------------------
// Dispatch: bucket (token, expert) slots by expert with atomics.
// NOTE: topk_indices is int32 on disk (jax silently downcasts int64
// when x64 is disabled). Reading it as int64 was the R3/R4 trap.
// ------------------------------------------------------------------
__global__ void k_dispatch(const int* __restrict__ idx,
                           const float* __restrict__ w) {
    int s = blockIdx.x * blockDim.x + threadIdx.x;
    if (s >= TKS) return;
    int e = idx[s];
    if ((unsigned)e >= NE) return;   // defensive: never trap on bad data
    int pos = atomicAdd(&g_counts[e], 1);
    if (pos < CAP) {
        g_tok[e * CAP + pos] = s / KTOP;
        g_wgt[e * CAP + pos] = w[s];
    }
}

// ------------------------------------------------------------------
// Tiling: TM=128 rows, TN=64 cols, TB=16 k-slice, 256 threads,
// 8x4 fragment per thread (rows ty+16i, cols tx+16j).
// A tile stored [m][k] row-major, 20-float rows (16B-aligned pad).
// Register-staged double buffering: LDG next tile -> compute -> STS.
// ------------------------------------------------------------------
#define TM 128
#define TN 64
#define TB 16
#define APAD 4   // row stride TB+APAD = 20 floats = 80B

// GEMM1: for each expert, h = silu(X Wg) * (X Wu). X gathered via g_tok.
__global__ __launch_bounds__(256)
void k_gemm1(const float* __restrict__ X,
             const float* __restrict__ Wg,
             const float* __restrict__ Wu) {
    const int e = blockIdx.z;
    int cnt = g_counts[e];
    if (cnt > CAP) cnt = CAP;
    const int row0 = blockIdx.y * TM;
    if (row0 >= cnt) return;
    const int col0 = blockIdx.x * TN;

    __shared__ __align__(16) float As[2][TM][TB + APAD];
    __shared__ __align__(16) float Bgs[2][TB][TN];
    __shared__ __align__(16) float Bus[2][TB][TN];
    __shared__ int toks[TM];

    const int tid = threadIdx.x;
    const int ty = tid >> 4;                  // 0..15
    const int tx = tid & 15;                  // 0..15

    if (tid < TM) {
        int r = row0 + tid;
        toks[tid] = (r < cnt) ? g_tok[e * CAP + r] : -1;
    }
    __syncthreads();

    const float* wg_e = Wg + (size_t)e * DIM * FF;
    const float* wu_e = Wu + (size_t)e * DIM * FF;

    // A-load mapping: 128 rows x 16 k = 512 float4; 2 per thread
    const int am0 = tid >> 2;                 // 0..63 (row; +64 for 2nd)
    const int ak0 = (tid & 3) * 4;            // 0,4,8,12
    const int tkA0 = toks[am0];
    const int tkA1 = toks[am0 + 64];
    const float* srcA0 = (tkA0 >= 0) ? X + (size_t)tkA0 * DIM + ak0 : nullptr;
    const float* srcA1 = (tkA1 >= 0) ? X + (size_t)tkA1 * DIM + ak0 : nullptr;

    // B-load mapping: 16k x 64n = 256 float4; 1 per thread per matrix
    const int bk = tid >> 4;                  // 0..15
    const int bn = (tid & 15) * 4;            // 0..60
    const size_t boff0 = (size_t)bk * FF + col0 + bn;

    const float4 z4 = make_float4(0.f, 0.f, 0.f, 0.f);
    const int NK = DIM / TB;                  // 64 k-tiles

    // prologue: load tile 0 into registers, store to stage 0
    float4 rA0 = srcA0 ? *(const float4*)(srcA0) : z4;
    float4 rA1 = srcA1 ? *(const float4*)(srcA1) : z4;
    float4 rBg = *(const float4*)(wg_e + boff0);
    float4 rBu = *(const float4*)(wu_e + boff0);
    *(float4*)&As[0][am0][ak0]      = rA0;
    *(float4*)&As[0][am0 + 64][ak0] = rA1;
    *(float4*)&Bgs[0][bk][bn] = rBg;
    *(float4*)&Bus[0][bk][bn] = rBu;
    __syncthreads();

    float accG[8][4] = {};
    float accU[8][4] = {};

    for (int t = 0; t < NK; t++) {
        const int cur = t & 1, nxt = cur ^ 1;
        const bool more = (t + 1 < NK);
        // issue next-tile loads early (latency hidden behind compute)
        if (more) {
            const int k1 = (t + 1) * TB;
            rA0 = srcA0 ? *(const float4*)(srcA0 + k1) : z4;
            rA1 = srcA1 ? *(const float4*)(srcA1 + k1) : z4;
            const size_t bo = boff0 + (size_t)k1 * FF;
            rBg = *(const float4*)(wg_e + bo);
            rBu = *(const float4*)(wu_e + bo);
        }

        #pragma unroll
        for (int kk = 0; kk < TB; kk++) {
            float a[8], bg[4], bu[4];
            #pragma unroll
            for (int i = 0; i < 8; i++) a[i] = As[cur][ty + 16 * i][kk];
            #pragma unroll
            for (int j = 0; j < 4; j++) {
                bg[j] = Bgs[cur][kk][tx + 16 * j];
                bu[j] = Bus[cur][kk][tx + 16 * j];
            }
            #pragma unroll
            for (int i = 0; i < 8; i++)
                #pragma unroll
                for (int j = 0; j < 4; j++) {
                    accG[i][j] = fmaf(a[i], bg[j], accG[i][j]);
                    accU[i][j] = fmaf(a[i], bu[j], accU[i][j]);
                }
        }

        if (more) {
            *(float4*)&As[nxt][am0][ak0]      = rA0;
            *(float4*)&As[nxt][am0 + 64][ak0] = rA1;
            *(float4*)&Bgs[nxt][bk][bn] = rBg;
            *(float4*)&Bus[nxt][bk][bn] = rBu;
            __syncthreads();
        }
    }

    // epilogue: h = silu(g) * u
    #pragma unroll
    for (int i = 0; i < 8; i++) {
        int r = row0 + ty + 16 * i;
        if (r >= cnt) continue;
        size_t base = ((size_t)e * CAP + r) * FF + col0;
        #pragma unroll
        for (int j = 0; j < 4; j++) {
            float g = accG[i][j];
            float s = g / (1.f + expf(-g));
            g_h[base + tx + 16 * j] = s * accU[i][j];
        }
    }
}

// GEMM2: y = h Wd, weighted atomic scatter-add into out[token].
__global__ __launch_bounds__(256)
void k_gemm2(const float* __restrict__ Wd,
             float* __restrict__ out) {
    const int e = blockIdx.z;
    int cnt = g_counts[e];
    if (cnt > CAP) cnt = CAP;
    const int row0 = blockIdx.y * TM;
    if (row0 >= cnt) return;
    const int col0 = blockIdx.x * TN;

    __shared__ __align__(16) float As[2][TM][TB + APAD];
    __shared__ __align__(16) float Bds[2][TB][TN];
    __shared__ int   toks[TM];
    __shared__ float wts[TM];

    const int tid = threadIdx.x;
    const int ty = tid >> 4;
    const int tx = tid & 15;

    if (tid < TM) {
        int r = row0 + tid;
        if (r < cnt) {
            toks[tid] = g_tok[e * CAP + r];
            wts[tid]  = g_wgt[e * CAP + r];
        } else {
            toks[tid] = -1;
            wts[tid]  = 0.f;
        }
    }
    __syncthreads();

    const float* wd_e = Wd + (size_t)e * FF * DIM;
    const float* h_e  = g_h + ((size_t)e * CAP) * FF;

    const int am0 = tid >> 2;
    const int ak0 = (tid & 3) * 4;
    const int rAr0 = row0 + am0, rAr1 = row0 + am0 + 64;
    const float* srcA0 = (rAr0 < cnt) ? h_e + (size_t)rAr0 * FF + ak0 : nullptr;
    const float* srcA1 = (rAr1 < cnt) ? h_e + (size_t)rAr1 * FF + ak0 : nullptr;

    const int bk = tid >> 4;
    const int bn = (tid & 15) * 4;
    const size_t boff0 = (size_t)bk * DIM + col0 + bn;

    const float4 z4 = make_float4(0.f, 0.f, 0.f, 0.f);
    const int NK = FF / TB;                   // 32 k-tiles

    float4 rA0 = srcA0 ? *(const float4*)(srcA0) : z4;
    float4 rA1 = srcA1 ? *(const float4*)(srcA1) : z4;
    float4 rBd = *(const float4*)(wd_e + boff0);
    *(float4*)&As[0][am0][ak0]      = rA0;
    *(float4*)&As[0][am0 + 64][ak0] = rA1;
    *(float4*)&Bds[0][bk][bn] = rBd;
    __syncthreads();

    float acc[8][4] = {};

    for (int t = 0; t < NK; t++) {
        const int cur = t & 1, nxt = cur ^ 1;
        const bool more = (t + 1 < NK);
        if (more) {
            const int k1 = (t + 1) * TB;
            rA0 = srcA0 ? *(const float4*)(srcA0 + k1) : z4;
            rA1 = srcA1 ? *(const float4*)(srcA1 + k1) : z4;
            rBd = *(const float4*)(wd_e + boff0 + (size_t)k1 * DIM);
        }

        #pragma unroll
        for (int kk = 0; kk < TB; kk++) {
            float a[8], b[4];
            #pragma unroll
            for (int i = 0; i < 8; i++) a[i] = As[cur][ty + 16 * i][kk];
            #pragma unroll
            for (int j = 0; j < 4; j++) b[j] = Bds[cur][kk][tx + 16 * j];
            #pragma unroll
            for (int i = 0; i < 8; i++)
                #pragma unroll
                for (int j = 0; j < 4; j++)
                    acc[i][j] = fmaf(a[i], b[j], acc[i][j]);
        }

        if (more) {
            *(float4*)&As[nxt][am0][ak0]      = rA0;
            *(float4*)&As[nxt][am0 + 64][ak0] = rA1;
            *(float4*)&Bds[nxt][bk][bn] = rBd;
            __syncthreads();
        }
    }

    // weighted scatter-add combine
    #pragma unroll
    for (int i = 0; i < 8; i++) {
        int m = ty + 16 * i;
        int r = row0 + m;
        if (r >= cnt) continue;
        int tk = toks[m];
        float wv = wts[m];
        float* orow = out + (size_t)tk * DIM + col0;
        #pragma unroll
        for (int j = 0; j < 4; j++)
            atomicAdd(&orow[tx + 16 * j], wv * acc[i][j]);
    }
}

// ------------------------------------------------------------------
// Launch
// ------------------------------------------------------------------
extern "C" void kernel_launch(void* const* d_in, const int* in_sizes, int n_in,
                              void* d_out, int out_size) {
    const float* x   = (const float*)d_in[0];   // [T, D] f32
    const int*   idx = (const int*)d_in[1];     // [T, K] int32 (jax x64 off!)
    const float* w   = (const float*)d_in[2];   // [T, K] f32
    const float* wg  = (const float*)d_in[3];   // [E, D, F] f32
    const float* wu  = (const float*)d_in[4];   // [E, D, F] f32
    const float* wd  = (const float*)d_in[5];   // [E, F, D] f32
    float* out = (float*)d_out;                 // [T, D] f32

    k_zero<<<512, 256>>>((float4*)out);
    k_dispatch<<<(TKS + 255) / 256, 256>>>(idx, w);
    k_gemm1<<<dim3(FF / TN, CAP / TM, NE), 256>>>(x, wg, wu);
    k_gemm2<<<dim3(DIM / TN, CAP / TM, NE), 256>>>(wd, out);
}

// round 6
// speedup vs baseline: 1.1742x; 1.1742x over previous
#include <cuda_runtime.h>
#include <cuda_bf16.h>
#include <cstdint>

// Problem constants (fixed shapes from reference)
#define NE   16          // experts
#define KTOP 2           // top-k
#define DIM  1024        // model dim
#define FF   512         // ffn dim
#define NT   4096        // tokens
#define CAP  2048        // per-expert capacity
#define TKS  (NT*KTOP)   // total slots

// ---- device scratch (allocation-free rule: __device__ globals) ----
__device__ int   g_counts[NE];
__device__ int   g_tok[NE*CAP];          // token id per (expert, pos)
__device__ float g_wgt[NE*CAP];          // routing weight per (expert, pos)
__device__ float g_h[(size_t)NE*CAP*FF]; // intermediate h, 64 MB

// ---- packed f32x2 helpers (Blackwell FFMA2: 2x fp32 throughput) ----
__device__ __forceinline__ unsigned long long pk2(float lo, float hi) {
    unsigned long long r;
    asm("mov.b64 %0, {%1, %2};" : "=l"(r) : "f"(lo), "f"(hi));
    return r;
}
__device__ __forceinline__ void ffma2(unsigned long long& acc,
                                      unsigned long long a,
                                      unsigned long long b) {
    asm("fma.rn.f32x2 %0, %1, %2, %0;" : "+l"(acc) : "l"(a), "l"(b));
}
__device__ __forceinline__ float2 upk2(unsigned long long v) {
    float2 f;
    asm("mov.b64 {%0, %1}, %2;" : "=f"(f.x), "=f"(f.y) : "l"(v));
    return f;
}

// ------------------------------------------------------------------
// Zero output + counters (vectorized)
// ------------------------------------------------------------------
__global__ void k_zero(float4* __restrict__ out4) {
    int i = blockIdx.x * blockDim.x + threadIdx.x;
    if (i < NE) g_counts[i] = 0;
    const float4 z = make_float4(0.f, 0.f, 0.f, 0.f);
    for (int j = i; j < NT * DIM / 4; j += gridDim.x * blockDim.x) out4[j] = z;
}

// ------------------------------------------------------------------
// Dispatch (topk_indices is int32 on disk — jax x64 disabled)
// ------------------------------------------------------------------
__global__ void k_dispatch(const int* __restrict__ idx,
                           const float* __restrict__ w) {
    int s = blockIdx.x * blockDim.x + threadIdx.x;
    if (s >= TKS) return;
    int e = idx[s];
    if ((unsigned)e >= NE) return;
    int pos = atomicAdd(&g_counts[e], 1);
    if (pos < CAP) {
        g_tok[e * CAP + pos] = s / KTOP;
        g_wgt[e * CAP + pos] = w[s];
    }
}

// ------------------------------------------------------------------
// Tiling: TM=128, TN=64, TB=16, 256 threads.
// Fragment: rows ty*8..ty*8+7 (contiguous), cols tx*4..tx*4+3
// (contiguous) -> a-frag 2x LDS.128 (broadcast), b-frag 1x LDS.128.
// FFMA2 accumulators paired along rows.
// A tile [k][m] layout, row stride TM+4 (16B aligned).
// ------------------------------------------------------------------
#define TM 128
#define TN 64
#define TB 16
#define ASTRIDE (TM + 4)

// GEMM1: h = silu(X Wg) * (X Wu), X gathered via g_tok.
__global__ __launch_bounds__(256)
void k_gemm1(const float* __restrict__ X,
             const float* __restrict__ Wg,
             const float* __restrict__ Wu) {
    const int e = blockIdx.z;
    int cnt = g_counts[e];
    if (cnt > CAP) cnt = CAP;
    const int row0 = blockIdx.y * TM;
    if (row0 >= cnt) return;
    const int col0 = blockIdx.x * TN;

    __shared__ __align__(16) float As[2][TB][ASTRIDE];
    __shared__ __align__(16) float Bgs[2][TB][TN];
    __shared__ __align__(16) float Bus[2][TB][TN];
    __shared__ int toks[TM];

    const int tid = threadIdx.x;
    const int ty = tid >> 4;                  // 0..15 -> rows ty*8..+7
    const int tx = tid & 15;                  // 0..15 -> cols tx*4..+3

    if (tid < TM) {
        int r = row0 + tid;
        toks[tid] = (r < cnt) ? g_tok[e * CAP + r] : -1;
    }
    __syncthreads();

    const float* wg_e = Wg + (size_t)e * DIM * FF;
    const float* wu_e = Wu + (size_t)e * DIM * FF;

    // A staging: 128 rows x 16 k = 512 float4; 2 per thread
    const int am0 = tid >> 2;                 // 0..63 (+64 second)
    const int ak0 = (tid & 3) * 4;            // 0,4,8,12
    const int tkA0 = toks[am0];
    const int tkA1 = toks[am0 + 64];
    const float* srcA0 = (tkA0 >= 0) ? X + (size_t)tkA0 * DIM + ak0 : nullptr;
    const float* srcA1 = (tkA1 >= 0) ? X + (size_t)tkA1 * DIM + ak0 : nullptr;

    // B staging: 16k x 64n = 256 float4; 1 per thread per matrix
    const int bk = tid >> 4;
    const int bn = (tid & 15) * 4;
    const size_t boff0 = (size_t)bk * FF + col0 + bn;

    const float4 z4 = make_float4(0.f, 0.f, 0.f, 0.f);
    const int NK = DIM / TB;                  // 64

    float4 rA0 = srcA0 ? *(const float4*)(srcA0) : z4;
    float4 rA1 = srcA1 ? *(const float4*)(srcA1) : z4;
    float4 rBg = *(const float4*)(wg_e + boff0);
    float4 rBu = *(const float4*)(wu_e + boff0);
    #pragma unroll
    for (int i = 0; i < 4; i++) {
        As[0][ak0 + i][am0]      = (&rA0.x)[i];
        As[0][ak0 + i][am0 + 64] = (&rA1.x)[i];
    }
    *(float4*)&Bgs[0][bk][bn] = rBg;
    *(float4*)&Bus[0][bk][bn] = rBu;
    __syncthreads();

    unsigned long long accG2[4][4] = {};   // rows (2ip,2ip+1) x col j
    unsigned long long accU2[4][4] = {};

    for (int t = 0; t < NK; t++) {
        const int cur = t & 1, nxt = cur ^ 1;
        const bool more = (t + 1 < NK);
        if (more) {
            const int k1 = (t + 1) * TB;
            rA0 = srcA0 ? *(const float4*)(srcA0 + k1) : z4;
            rA1 = srcA1 ? *(const float4*)(srcA1 + k1) : z4;
            const size_t bo = boff0 + (size_t)k1 * FF;
            rBg = *(const float4*)(wg_e + bo);
            rBu = *(const float4*)(wu_e + bo);
        }

        #pragma unroll
        for (int kk = 0; kk < TB; kk++) {
            float4 a01 = *(const float4*)&As[cur][kk][ty * 8];
            float4 a23 = *(const float4*)&As[cur][kk][ty * 8 + 4];
            float4 bg4 = *(const float4*)&Bgs[cur][kk][tx * 4];
            float4 bu4 = *(const float4*)&Bus[cur][kk][tx * 4];
            unsigned long long a2[4] = {
                pk2(a01.x, a01.y), pk2(a01.z, a01.w),
                pk2(a23.x, a23.y), pk2(a23.z, a23.w) };
            unsigned long long bg2[4] = {
                pk2(bg4.x, bg4.x), pk2(bg4.y, bg4.y),
                pk2(bg4.z, bg4.z), pk2(bg4.w, bg4.w) };
            unsigned long long bu2[4] = {
                pk2(bu4.x, bu4.x), pk2(bu4.y, bu4.y),
                pk2(bu4.z, bu4.z), pk2(bu4.w, bu4.w) };
            #pragma unroll
            for (int ip = 0; ip < 4; ip++)
                #pragma unroll
                for (int j = 0; j < 4; j++) {
                    ffma2(accG2[ip][j], a2[ip], bg2[j]);
                    ffma2(accU2[ip][j], a2[ip], bu2[j]);
                }
        }

        if (more) {
            #pragma unroll
            for (int i = 0; i < 4; i++) {
                As[nxt][ak0 + i][am0]      = (&rA0.x)[i];
                As[nxt][ak0 + i][am0 + 64] = (&rA1.x)[i];
            }
            *(float4*)&Bgs[nxt][bk][bn] = rBg;
            *(float4*)&Bus[nxt][bk][bn] = rBu;
            __syncthreads();
        }
    }

    // epilogue: h = silu(g) * u, float4 stores
    #pragma unroll
    for (int ii = 0; ii < 8; ii++) {
        int r = row0 + ty * 8 + ii;
        if (r >= cnt) continue;
        size_t base = ((size_t)e * CAP + r) * FF + col0 + tx * 4;
        float4 hv;
        #pragma unroll
        for (int j = 0; j < 4; j++) {
            float2 g2 = upk2(accG2[ii >> 1][j]);
            float2 u2 = upk2(accU2[ii >> 1][j]);
            float g = (ii & 1) ? g2.y : g2.x;
            float u = (ii & 1) ? u2.y : u2.x;
            (&hv.x)[j] = (g / (1.f + expf(-g))) * u;
        }
        *(float4*)(g_h + base) = hv;
    }
}

// GEMM2: y = h Wd, weighted atomic scatter-add into out[token].
__global__ __launch_bounds__(256)
void k_gemm2(const float* __restrict__ Wd,
             float* __restrict__ out) {
    const int e = blockIdx.z;
    int cnt = g_counts[e];
    if (cnt > CAP) cnt = CAP;
    const int row0 = blockIdx.y * TM;
    if (row0 >= cnt) return;
    const int col0 = blockIdx.x * TN;

    __shared__ __align__(16) float As[2][TB][ASTRIDE];
    __shared__ __align__(16) float Bds[2][TB][TN];
    __shared__ int   toks[TM];
    __shared__ float wts[TM];

    const int tid = threadIdx.x;
    const int ty = tid >> 4;
    const int tx = tid & 15;

    if (tid < TM) {
        int r = row0 + tid;
        if (r < cnt) {
            toks[tid] = g_tok[e * CAP + r];
            wts[tid]  = g_wgt[e * CAP + r];
        } else {
            toks[tid] = -1;
            wts[tid]  = 0.f;
        }
    }
    __syncthreads();

    const float* wd_e = Wd + (size_t)e * FF * DIM;
    const float* h_e  = g_h + ((size_t)e * CAP) * FF;

    const int am0 = tid >> 2;
    const int ak0 = (tid & 3) * 4;
    const int rAr0 = row0 + am0, rAr1 = row0 + am0 + 64;
    const float* srcA0 = (rAr0 < cnt) ? h_e + (size_t)rAr0 * FF + ak0 : nullptr;
    const float* srcA1 = (rAr1 < cnt) ? h_e + (size_t)rAr1 * FF + ak0 : nullptr;

    const int bk = tid >> 4;
    const int bn = (tid & 15) * 4;
    const size_t boff0 = (size_t)bk * DIM + col0 + bn;

    const float4 z4 = make_float4(0.f, 0.f, 0.f, 0.f);
    const int NK = FF / TB;                   // 32

    float4 rA0 = srcA0 ? *(const float4*)(srcA0) : z4;
    float4 rA1 = srcA1 ? *(const float4*)(srcA1) : z4;
    float4 rBd = *(const float4*)(wd_e + boff0);
    #pragma unroll
    for (int i = 0; i < 4; i++) {
        As[0][ak0 + i][am0]      = (&rA0.x)[i];
        As[0][ak0 + i][am0 + 64] = (&rA1.x)[i];
    }
    *(float4*)&Bds[0][bk][bn] = rBd;
    __syncthreads();

    unsigned long long acc2[4][4] = {};

    for (int t = 0; t < NK; t++) {
        const int cur = t & 1, nxt = cur ^ 1;
        const bool more = (t + 1 < NK);
        if (more) {
            const int k1 = (t + 1) * TB;
            rA0 = srcA0 ? *(const float4*)(srcA0 + k1) : z4;
            rA1 = srcA1 ? *(const float4*)(srcA1 + k1) : z4;
            rBd = *(const float4*)(wd_e + boff0 + (size_t)k1 * DIM);
        }

        #pragma unroll
        for (int kk = 0; kk < TB; kk++) {
            float4 a01 = *(const float4*)&As[cur][kk][ty * 8];
            float4 a23 = *(const float4*)&As[cur][kk][ty * 8 + 4];
            float4 b4  = *(const float4*)&Bds[cur][kk][tx * 4];
            unsigned long long a2[4] = {
                pk2(a01.x, a01.y), pk2(a01.z, a01.w),
                pk2(a23.x, a23.y), pk2(a23.z, a23.w) };
            unsigned long long b2[4] = {
                pk2(b4.x, b4.x), pk2(b4.y, b4.y),
                pk2(b4.z, b4.z), pk2(b4.w, b4.w) };
            #pragma unroll
            for (int ip = 0; ip < 4; ip++)
                #pragma unroll
                for (int j = 0; j < 4; j++)
                    ffma2(acc2[ip][j], a2[ip], b2[j]);
        }

        if (more) {
            #pragma unroll
            for (int i = 0; i < 4; i++) {
                As[nxt][ak0 + i][am0]      = (&rA0.x)[i];
                As[nxt][ak0 + i][am0 + 64] = (&rA1.x)[i];
            }
            *(float4*)&Bds[nxt][bk][bn] = rBd;
            __syncthreads();
        }
    }

    // weighted scatter-add combine
    #pragma unroll
    for (int ii = 0; ii < 8; ii++) {
        int m = ty * 8 + ii;
        int r = row0 + m;
        if (r >= cnt) continue;
        int tk = toks[m];
        float wv = wts[m];
        float* orow = out + (size_t)tk * DIM + col0 + tx * 4;
        #pragma unroll
        for (int j = 0; j < 4; j++) {
            float2 y2 = upk2(acc2[ii >> 1][j]);
            float y = (ii & 1) ? y2.y : y2.x;
            atomicAdd(&orow[j], wv * y);
        }
    }
}

// ------------------------------------------------------------------
// Launch
// ------------------------------------------------------------------
extern "C" void kernel_launch(void* const* d_in, const int* in_sizes, int n_in,
                              void* d_out, int out_size) {
    const float* x   = (const float*)d_in[0];   // [T, D] f32
    const int*   idx = (const int*)d_in[1];     // [T, K] int32
    const float* w   = (const float*)d_in[2];   // [T, K] f32
    const float* wg  = (const float*)d_in[3];   // [E, D, F] f32
    const float* wu  = (const float*)d_in[4];   // [E, D, F] f32
    const float* wd  = (const float*)d_in[5];   // [E, F, D] f32
    float* out = (float*)d_out;                 // [T, D] f32

    k_zero<<<512, 256>>>((float4*)out);
    k_dispatch<<<(TKS + 255) / 256, 256>>>(idx, w);
    k_gemm1<<<dim3(FF / TN, CAP / TM, NE), 256>>>(x, wg, wu);
    k_gemm2<<<dim3(DIM / TN, CAP / TM, NE), 256>>>(wd, out);
}

// round 7
// speedup vs baseline: 1.1782x; 1.0034x over previous
#include <cuda_runtime.h>
#include <cuda_bf16.h>
#include <cstdint>

// Problem constants (fixed shapes from reference)
#define NE   16          // experts
#define KTOP 2           // top-k
#define DIM  1024        // model dim
#define FF   512         // ffn dim
#define NT   4096        // tokens
#define CAP  2048        // per-expert capacity
#define TKS  (NT*KTOP)   // total slots

typedef unsigned long long u64;

// ---- device scratch (allocation-free rule: __device__ globals) ----
__device__ int   g_counts[NE];
__device__ int   g_tok[NE*CAP];
__device__ float g_wgt[NE*CAP];
__device__ float g_h[(size_t)NE*CAP*FF]; // intermediate h, 64 MB

// ---- packed f32x2 helpers (Blackwell FFMA2) ----
__device__ __forceinline__ u64 pk2(float lo, float hi) {
    u64 r;
    asm("mov.b64 %0, {%1, %2};" : "=l"(r) : "f"(lo), "f"(hi));
    return r;
}
__device__ __forceinline__ void ffma2(u64& acc, u64 a, u64 b) {
    asm("fma.rn.f32x2 %0, %1, %2, %0;" : "+l"(acc) : "l"(a), "l"(b));
}
__device__ __forceinline__ float2 upk2(u64 v) {
    float2 f;
    asm("mov.b64 {%0, %1}, %2;" : "=f"(f.x), "=f"(f.y) : "l"(v));
    return f;
}

// ------------------------------------------------------------------
__global__ void k_zero(float4* __restrict__ out4) {
    int i = blockIdx.x * blockDim.x + threadIdx.x;
    if (i < NE) g_counts[i] = 0;
    const float4 z = make_float4(0.f, 0.f, 0.f, 0.f);
    for (int j = i; j < NT * DIM / 4; j += gridDim.x * blockDim.x) out4[j] = z;
}

// topk_indices is int32 on disk (jax x64 disabled)
__global__ void k_dispatch(const int* __restrict__ idx,
                           const float* __restrict__ w) {
    int s = blockIdx.x * blockDim.x + threadIdx.x;
    if (s >= TKS) return;
    int e = idx[s];
    if ((unsigned)e >= NE) return;
    int pos = atomicAdd(&g_counts[e], 1);
    if (pos < CAP) {
        g_tok[e * CAP + pos] = s / KTOP;
        g_wgt[e * CAP + pos] = w[s];
    }
}

// ------------------------------------------------------------------
// Tiling: TM=128, TN=64, TB=16, 256 threads, 8x4 frags.
// A tile [k][m], stride 132 (16B aligned rows); pairs along rows read
// directly as ulonglong2 (no repack movs). Fragment double-buffering
// hides the 29-cyc LDS latency; smem tiles double-buffered over k.
// ------------------------------------------------------------------
#define TM 128
#define TN 64
#define TB 16
#define ASTRIDE (TM + 4)

// GEMM1: h = silu(X Wg) * (X Wu), X gathered via g_tok.
__global__ __launch_bounds__(256)
void k_gemm1(const float* __restrict__ X,
             const float* __restrict__ Wg,
             const float* __restrict__ Wu) {
    const int e = blockIdx.z;
    int cnt = g_counts[e];
    if (cnt > CAP) cnt = CAP;
    const int row0 = blockIdx.y * TM;
    if (row0 >= cnt) return;
    const int col0 = blockIdx.x * TN;

    __shared__ __align__(16) float As[2][TB][ASTRIDE];
    __shared__ __align__(16) float Bgs[2][TB][TN];
    __shared__ __align__(16) float Bus[2][TB][TN];
    __shared__ int toks[TM];

    const int tid = threadIdx.x;
    const int ty = tid >> 4;                  // rows ty*8..+7
    const int tx = tid & 15;                  // cols tx*4..+3

    if (tid < TM) {
        int r = row0 + tid;
        toks[tid] = (r < cnt) ? g_tok[e * CAP + r] : -1;
    }
    __syncthreads();

    const float* wg_e = Wg + (size_t)e * DIM * FF;
    const float* wu_e = Wu + (size_t)e * DIM * FF;

    const int am0 = tid >> 2;                 // 0..63 (+64 second)
    const int ak0 = (tid & 3) * 4;
    const int tkA0 = toks[am0];
    const int tkA1 = toks[am0 + 64];
    const float* srcA0 = (tkA0 >= 0) ? X + (size_t)tkA0 * DIM + ak0 : nullptr;
    const float* srcA1 = (tkA1 >= 0) ? X + (size_t)tkA1 * DIM + ak0 : nullptr;

    const int bk = tid >> 4;
    const int bn = (tid & 15) * 4;
    const size_t boff0 = (size_t)bk * FF + col0 + bn;

    const float4 z4 = make_float4(0.f, 0.f, 0.f, 0.f);
    const int NK = DIM / TB;                  // 64

    float4 rA0 = srcA0 ? *(const float4*)(srcA0) : z4;
    float4 rA1 = srcA1 ? *(const float4*)(srcA1) : z4;
    float4 rBg = *(const float4*)(wg_e + boff0);
    float4 rBu = *(const float4*)(wu_e + boff0);
    #pragma unroll
    for (int i = 0; i < 4; i++) {
        As[0][ak0 + i][am0]      = (&rA0.x)[i];
        As[0][ak0 + i][am0 + 64] = (&rA1.x)[i];
    }
    *(float4*)&Bgs[0][bk][bn] = rBg;
    *(float4*)&Bus[0][bk][bn] = rBu;
    __syncthreads();

    u64 accG2[4][4] = {};
    u64 accU2[4][4] = {};

    // fragment buffers (raw loads; dup at use rides alu pipe)
    u64    fa[2][4];
    float4 fg[2], fu[2];

    for (int t = 0; t < NK; t++) {
        const int cur = t & 1, nxt = cur ^ 1;
        const bool more = (t + 1 < NK);
        if (more) {
            const int k1 = (t + 1) * TB;
            rA0 = srcA0 ? *(const float4*)(srcA0 + k1) : z4;
            rA1 = srcA1 ? *(const float4*)(srcA1 + k1) : z4;
            const size_t bo = boff0 + (size_t)k1 * FF;
            rBg = *(const float4*)(wg_e + bo);
            rBu = *(const float4*)(wu_e + bo);
        }

        // prime fragment 0
        {
            ulonglong2 a01 = *(const ulonglong2*)&As[cur][0][ty * 8];
            ulonglong2 a23 = *(const ulonglong2*)&As[cur][0][ty * 8 + 4];
            fa[0][0] = a01.x; fa[0][1] = a01.y; fa[0][2] = a23.x; fa[0][3] = a23.y;
            fg[0] = *(const float4*)&Bgs[cur][0][tx * 4];
            fu[0] = *(const float4*)&Bus[cur][0][tx * 4];
        }

        #pragma unroll
        for (int kk = 0; kk < TB; kk++) {
            const int cb = kk & 1, nb = cb ^ 1;
            if (kk + 1 < TB) {
                ulonglong2 a01 = *(const ulonglong2*)&As[cur][kk + 1][ty * 8];
                ulonglong2 a23 = *(const ulonglong2*)&As[cur][kk + 1][ty * 8 + 4];
                fa[nb][0] = a01.x; fa[nb][1] = a01.y; fa[nb][2] = a23.x; fa[nb][3] = a23.y;
                fg[nb] = *(const float4*)&Bgs[cur][kk + 1][tx * 4];
                fu[nb] = *(const float4*)&Bus[cur][kk + 1][tx * 4];
            }
            u64 g2[4] = { pk2(fg[cb].x, fg[cb].x), pk2(fg[cb].y, fg[cb].y),
                          pk2(fg[cb].z, fg[cb].z), pk2(fg[cb].w, fg[cb].w) };
            u64 u2[4] = { pk2(fu[cb].x, fu[cb].x), pk2(fu[cb].y, fu[cb].y),
                          pk2(fu[cb].z, fu[cb].z), pk2(fu[cb].w, fu[cb].w) };
            #pragma unroll
            for (int ip = 0; ip < 4; ip++)
                #pragma unroll
                for (int j = 0; j < 4; j++) {
                    ffma2(accG2[ip][j], fa[cb][ip], g2[j]);
                    ffma2(accU2[ip][j], fa[cb][ip], u2[j]);
                }
        }

        if (more) {
            #pragma unroll
            for (int i = 0; i < 4; i++) {
                As[nxt][ak0 + i][am0]      = (&rA0.x)[i];
                As[nxt][ak0 + i][am0 + 64] = (&rA1.x)[i];
            }
            *(float4*)&Bgs[nxt][bk][bn] = rBg;
            *(float4*)&Bus[nxt][bk][bn] = rBu;
            __syncthreads();
        }
    }

    // epilogue: h = silu(g) * u
    #pragma unroll
    for (int ii = 0; ii < 8; ii++) {
        int r = row0 + ty * 8 + ii;
        if (r >= cnt) continue;
        size_t base = ((size_t)e * CAP + r) * FF + col0 + tx * 4;
        float4 hv;
        #pragma unroll
        for (int j = 0; j < 4; j++) {
            float2 g2 = upk2(accG2[ii >> 1][j]);
            float2 u2 = upk2(accU2[ii >> 1][j]);
            float g = (ii & 1) ? g2.y : g2.x;
            float u = (ii & 1) ? u2.y : u2.x;
            (&hv.x)[j] = (g / (1.f + expf(-g))) * u;
        }
        *(float4*)(g_h + base) = hv;
    }
}

// GEMM2: y = h Wd, weighted atomic scatter-add into out[token].
__global__ __launch_bounds__(256)
void k_gemm2(const float* __restrict__ Wd,
             float* __restrict__ out) {
    const int e = blockIdx.z;
    int cnt = g_counts[e];
    if (cnt > CAP) cnt = CAP;
    const int row0 = blockIdx.y * TM;
    if (row0 >= cnt) return;
    const int col0 = blockIdx.x * TN;

    __shared__ __align__(16) float As[2][TB][ASTRIDE];
    __shared__ __align__(16) float Bds[2][TB][TN];
    __shared__ int   toks[TM];
    __shared__ float wts[TM];

    const int tid = threadIdx.x;
    const int ty = tid >> 4;
    const int tx = tid & 15;

    if (tid < TM) {
        int r = row0 + tid;
        if (r < cnt) {
            toks[tid] = g_tok[e * CAP + r];
            wts[tid]  = g_wgt[e * CAP + r];
        } else {
            toks[tid] = -1;
            wts[tid]  = 0.f;
        }
    }
    __syncthreads();

    const float* wd_e = Wd + (size_t)e * FF * DIM;
    const float* h_e  = g_h + ((size_t)e * CAP) * FF;

    const int am0 = tid >> 2;
    const int ak0 = (tid & 3) * 4;
    const int rAr0 = row0 + am0, rAr1 = row0 + am0 + 64;
    const float* srcA0 = (rAr0 < cnt) ? h_e + (size_t)rAr0 * FF + ak0 : nullptr;
    const float* srcA1 = (rAr1 < cnt) ? h_e + (size_t)rAr1 * FF + ak0 : nullptr;

    const int bk = tid >> 4;
    const int bn = (tid & 15) * 4;
    const size_t boff0 = (size_t)bk * DIM + col0 + bn;

    const float4 z4 = make_float4(0.f, 0.f, 0.f, 0.f);
    const int NK = FF / TB;                   // 32

    float4 rA0 = srcA0 ? *(const float4*)(srcA0) : z4;
    float4 rA1 = srcA1 ? *(const float4*)(srcA1) : z4;
    float4 rBd = *(const float4*)(wd_e + boff0);
    #pragma unroll
    for (int i = 0; i < 4; i++) {
        As[0][ak0 + i][am0]      = (&rA0.x)[i];
        As[0][ak0 + i][am0 + 64] = (&rA1.x)[i];
    }
    *(float4*)&Bds[0][bk][bn] = rBd;
    __syncthreads();

    u64 acc2[4][4] = {};

    u64    fa[2][4];
    float4 fb[2];

    for (int t = 0; t < NK; t++) {
        const int cur = t & 1, nxt = cur ^ 1;
        const bool more = (t + 1 < NK);
        if (more) {
            const int k1 = (t + 1) * TB;
            rA0 = srcA0 ? *(const float4*)(srcA0 + k1) : z4;
            rA1 = srcA1 ? *(const float4*)(srcA1 + k1) : z4;
            rBd = *(const float4*)(wd_e + boff0 + (size_t)k1 * DIM);
        }

        {
            ulonglong2 a01 = *(const ulonglong2*)&As[cur][0][ty * 8];
            ulonglong2 a23 = *(const ulonglong2*)&As[cur][0][ty * 8 + 4];
            fa[0][0] = a01.x; fa[0][1] = a01.y; fa[0][2] = a23.x; fa[0][3] = a23.y;
            fb[0] = *(const float4*)&Bds[cur][0][tx * 4];
        }

        #pragma unroll
        for (int kk = 0; kk < TB; kk++) {
            const int cb = kk & 1, nb = cb ^ 1;
            if (kk + 1 < TB) {
                ulonglong2 a01 = *(const ulonglong2*)&As[cur][kk + 1][ty * 8];
                ulonglong2 a23 = *(const ulonglong2*)&As[cur][kk + 1][ty * 8 + 4];
                fa[nb][0] = a01.x; fa[nb][1] = a01.y; fa[nb][2] = a23.x; fa[nb][3] = a23.y;
                fb[nb] = *(const float4*)&Bds[cur][kk + 1][tx * 4];
            }
            u64 b2[4] = { pk2(fb[cb].x, fb[cb].x), pk2(fb[cb].y, fb[cb].y),
                          pk2(fb[cb].z, fb[cb].z), pk2(fb[cb].w, fb[cb].w) };
            #pragma unroll
            for (int ip = 0; ip < 4; ip++)
                #pragma unroll
                for (int j = 0; j < 4; j++)
                    ffma2(acc2[ip][j], fa[cb][ip], b2[j]);
        }

        if (more) {
            #pragma unroll
            for (int i = 0; i < 4; i++) {
                As[nxt][ak0 + i][am0]      = (&rA0.x)[i];
                As[nxt][ak0 + i][am0 + 64] = (&rA1.x)[i];
            }
            *(float4*)&Bds[nxt][bk][bn] = rBd;
            __syncthreads();
        }
    }

    // weighted scatter-add combine
    #pragma unroll
    for (int ii = 0; ii < 8; ii++) {
        int m = ty * 8 + ii;
        int r = row0 + m;
        if (r >= cnt) continue;
        int tk = toks[m];
        float wv = wts[m];
        float* orow = out + (size_t)tk * DIM + col0 + tx * 4;
        #pragma unroll
        for (int j = 0; j < 4; j++) {
            float2 y2 = upk2(acc2[ii >> 1][j]);
            float y = (ii & 1) ? y2.y : y2.x;
            atomicAdd(&orow[j], wv * y);
        }
    }
}

// ------------------------------------------------------------------
extern "C" void kernel_launch(void* const* d_in, const int* in_sizes, int n_in,
                              void* d_out, int out_size) {
    const float* x   = (const float*)d_in[0];   // [T, D] f32
    const int*   idx = (const int*)d_in[1];     // [T, K] int32
    const float* w   = (const float*)d_in[2];   // [T, K] f32
    const float* wg  = (const float*)d_in[3];   // [E, D, F] f32
    const float* wu  = (const float*)d_in[4];   // [E, D, F] f32
    const float* wd  = (const float*)d_in[5];   // [E, F, D] f32
    float* out = (float*)d_out;                 // [T, D] f32

    k_zero<<<512, 256>>>((float4*)out);
    k_dispatch<<<(TKS + 255) / 256, 256>>>(idx, w);
    k_gemm1<<<dim3(FF / TN, CAP / TM, NE), 256>>>(x, wg, wu);
    k_gemm2<<<dim3(DIM / TN, CAP / TM, NE), 256>>>(wd, out);
}

// round 14
// speedup vs baseline: 1.8804x; 1.5960x over previous
#include <cuda_runtime.h>
#include <cuda_bf16.h>
#include <cstdint>

// Problem constants
#define NE   16
#define KTOP 2
#define DIM  1024
#define FF   512
#define NT   4096
#define CAP  2048
#define TKS  (NT*KTOP)

#define KC   64      // K-chunk staged in smem
#define ASTR 72      // padded row stride (bf16 elems) -> conflict-free frags

typedef unsigned int u32;

// ---- device scratch ----
__device__ int   g_counts[NE];
__device__ int   g_tok[NE*CAP];
__device__ float g_wgt[NE*CAP];

__device__ __nv_bfloat16 s_xh[(size_t)NT*DIM];
__device__ __nv_bfloat16 s_xl[(size_t)NT*DIM];
__device__ __nv_bfloat16 s_wgh[(size_t)NE*FF*DIM];  // WgT [E][F][D]
__device__ __nv_bfloat16 s_wgl[(size_t)NE*FF*DIM];
__device__ __nv_bfloat16 s_wuh[(size_t)NE*FF*DIM];
__device__ __nv_bfloat16 s_wul[(size_t)NE*FF*DIM];
__device__ __nv_bfloat16 s_wdh[(size_t)NE*DIM*FF];  // WdT [E][D][F]
__device__ __nv_bfloat16 s_wdl[(size_t)NE*DIM*FF];
__device__ __nv_bfloat16 s_hh[(size_t)NE*CAP*FF];
__device__ __nv_bfloat16 s_hl[(size_t)NE*CAP*FF];

// ---- mma.sync m16n8k16 bf16 (sm_80+; no 'a'-gated features) ----
__device__ __forceinline__ void mma16816(float* c, const u32* a, const u32* b) {
    asm volatile(
        "mma.sync.aligned.m16n8k16.row.col.f32.bf16.bf16.f32 "
        "{%0,%1,%2,%3}, {%4,%5,%6,%7}, {%8,%9}, {%0,%1,%2,%3};"
        : "+f"(c[0]), "+f"(c[1]), "+f"(c[2]), "+f"(c[3])
        : "r"(a[0]), "r"(a[1]), "r"(a[2]), "r"(a[3]), "r"(b[0]), "r"(b[1]));
}

// A fragment (row-major m16k16): regs = {m0-7/k01, m8-15/k01, m0-7/k89, m8-15/k89}
__device__ __forceinline__ void lda(u32* a, const __nv_bfloat16* As,
                                    int mb, int kk, int g, int tg) {
    const __nv_bfloat16* p = As + (mb + g) * ASTR + kk + tg * 2;
    a[0] = *(const u32*)(p);
    a[1] = *(const u32*)(p + 8 * ASTR);
    a[2] = *(const u32*)(p + 8);
    a[3] = *(const u32*)(p + 8 * ASTR + 8);
}
// B fragment (n8k16, k-contiguous storage): regs = {n/k01, n/k89}
__device__ __forceinline__ void ldb(u32* b, const __nv_bfloat16* Bs,
                                    int nb, int kk, int g, int tg) {
    const __nv_bfloat16* p = Bs + (nb + g) * ASTR + kk + tg * 2;
    b[0] = *(const u32*)(p);
    b[1] = *(const u32*)(p + 8);
}

// ------------------------------------------------------------------
__global__ void k_zero(float4* __restrict__ out4) {
    int i = blockIdx.x * blockDim.x + threadIdx.x;
    if (i < NE) g_counts[i] = 0;
    const float4 z = make_float4(0.f, 0.f, 0.f, 0.f);
    for (int j = i; j < NT * DIM / 4; j += gridDim.x * blockDim.x) out4[j] = z;
}

__global__ void k_dispatch(const int* __restrict__ idx,
                           const float* __restrict__ w) {
    int s = blockIdx.x * blockDim.x + threadIdx.x;
    if (s >= TKS) return;
    int e = idx[s];
    if ((unsigned)e >= NE) return;
    int pos = atomicAdd(&g_counts[e], 1);
    if (pos < CAP) {
        g_tok[e * CAP + pos] = s / KTOP;
        g_wgt[e * CAP + pos] = w[s];
    }
}

// X fp32 -> hi/lo bf16
__global__ void k_convert_x(const float4* __restrict__ x4) {
    for (size_t i = blockIdx.x * blockDim.x + threadIdx.x;
         i < (size_t)NT * DIM / 4; i += (size_t)gridDim.x * blockDim.x) {
        float4 v = x4[i];
        __nv_bfloat16 h[4], l[4];
        #pragma unroll
        for (int j = 0; j < 4; j++) {
            float f = (&v.x)[j];
            h[j] = __float2bfloat16(f);
            l[j] = __float2bfloat16(f - __bfloat162float(h[j]));
        }
        *(uint2*)(s_xh + i * 4) = *(const uint2*)h;
        *(uint2*)(s_xl + i * 4) = *(const uint2*)l;
    }
}

// transpose + split: in [E][R][C] fp32 -> out [E][C][R] bf16 hi/lo
__global__ void k_convert_w(const float* __restrict__ in, int which, int R, int C) {
    __shared__ float tile[32][33];
    __nv_bfloat16 *dh, *dl;
    if (which == 0)      { dh = s_wgh; dl = s_wgl; }
    else if (which == 1) { dh = s_wuh; dl = s_wul; }
    else                 { dh = s_wdh; dl = s_wdl; }
    int e = blockIdx.z;
    int r0 = blockIdx.y * 32, c0 = blockIdx.x * 32;
    const float* src = in + (size_t)e * R * C;
    for (int i = threadIdx.y; i < 32; i += 8)
        tile[i][threadIdx.x] = src[(size_t)(r0 + i) * C + c0 + threadIdx.x];
    __syncthreads();
    for (int i = threadIdx.y; i < 32; i += 8) {
        float v = tile[threadIdx.x][i];
        __nv_bfloat16 h = __float2bfloat16(v);
        __nv_bfloat16 l = __float2bfloat16(v - __bfloat162float(h));
        size_t o = (size_t)e * R * C + (size_t)(c0 + i) * R + r0 + threadIdx.x;
        dh[o] = h;
        dl[o] = l;
    }
}

// ---- dynamic smem sizes ----
#define SM1_TOK  0
#define SM1_AH   512
#define SM1_AL   (SM1_AH + 128*ASTR*2)
#define SM1_BGH  (SM1_AL + 128*ASTR*2)
#define SM1_BGL  (SM1_BGH + 64*ASTR*2)
#define SM1_BUH  (SM1_BGL + 64*ASTR*2)
#define SM1_BUL  (SM1_BUH + 64*ASTR*2)
#define SMEM1    (SM1_BUL + 64*ASTR*2)    // 74240

#define SM2_TOK  0
#define SM2_WTS  512
#define SM2_AH   1024
#define SM2_AL   (SM2_AH + 128*ASTR*2)
#define SM2_BDH  (SM2_AL + 128*ASTR*2)
#define SM2_BDL  (SM2_BDH + 64*ASTR*2)
#define SMEM2    (SM2_BDL + 64*ASTR*2)    // 56320

// ------------------------------------------------------------------
// GEMM1 (HMMA): gate = X*WgT, up = X*WuT (bf16 split, fp32 acc);
// h = silu(gate)*up -> bf16 hi/lo.
// 8 warps: wm=wid&3 (32 rows), wn=wid>>2 (32 cols); warp does both mats.
// ------------------------------------------------------------------
__global__ __launch_bounds__(256)
void k_gemm1_mma() {
    const int e = blockIdx.z;
    int cnt = g_counts[e];
    if (cnt > CAP) cnt = CAP;
    const int row0 = blockIdx.y * 128;
    if (row0 >= cnt) return;
    const int col0 = blockIdx.x * 64;

    extern __shared__ char smem[];
    int* toks_s = (int*)(smem + SM1_TOK);
    __nv_bfloat16* Ah  = (__nv_bfloat16*)(smem + SM1_AH);
    __nv_bfloat16* Al  = (__nv_bfloat16*)(smem + SM1_AL);
    __nv_bfloat16* Bgh = (__nv_bfloat16*)(smem + SM1_BGH);
    __nv_bfloat16* Bgl = (__nv_bfloat16*)(smem + SM1_BGL);
    __nv_bfloat16* Buh = (__nv_bfloat16*)(smem + SM1_BUH);
    __nv_bfloat16* Bul = (__nv_bfloat16*)(smem + SM1_BUL);

    const int tid = threadIdx.x;
    const int wid = tid >> 5, lane = tid & 31;
    const int g = lane >> 2, tg = lane & 3;
    const int wm = wid & 3, wn = wid >> 2;

    if (tid < 128) {
        int r = row0 + tid;
        toks_s[tid] = (r < cnt) ? g_tok[e * CAP + r] : -1;
    }
    __syncthreads();

    const int arow = tid >> 1;
    const int aq = (tid & 1) * 4;
    const int tokA = toks_s[arow];

    float gc[2][4][4] = {};
    float uc[2][4][4] = {};

    for (int c = 0; c < DIM / KC; c++) {
        const int k0 = c * KC;
        // ---- stage A (gathered token rows), hi & lo ----
        {
            const uint4* sh = (const uint4*)(s_xh + (size_t)(tokA < 0 ? 0 : tokA) * DIM + k0);
            const uint4* sl = (const uint4*)(s_xl + (size_t)(tokA < 0 ? 0 : tokA) * DIM + k0);
            const uint4 z = make_uint4(0, 0, 0, 0);
            #pragma unroll
            for (int q = 0; q < 4; q++) {
                int ch = aq + q;
                *(uint4*)(Ah + arow * ASTR + ch * 8) = (tokA >= 0) ? sh[ch] : z;
                *(uint4*)(Al + arow * ASTR + ch * 8) = (tokA >= 0) ? sl[ch] : z;
            }
        }
        // ---- stage B: 4 arrays x 64 rows x 64 k ----
        #pragma unroll
        for (int it = 0; it < 8; it++) {
            int idxx = it * 256 + tid;
            int arr = idxx >> 9, rem = idxx & 511;
            int rowb = rem >> 3, ch = rem & 7;
            const __nv_bfloat16* src =
                (arr == 0) ? s_wgh : (arr == 1) ? s_wgl : (arr == 2) ? s_wuh : s_wul;
            __nv_bfloat16* dst =
                (arr == 0) ? Bgh : (arr == 1) ? Bgl : (arr == 2) ? Buh : Bul;
            uint4 v = ((const uint4*)(src + ((size_t)e * FF + col0 + rowb) * DIM + k0))[ch];
            *(uint4*)(dst + rowb * ASTR + ch * 8) = v;
        }
        __syncthreads();

        #pragma unroll
        for (int ks = 0; ks < KC / 16; ks++) {
            const int kk = ks * 16;
            u32 ah[2][4], al[2][4];
            #pragma unroll
            for (int mt = 0; mt < 2; mt++) {
                lda(ah[mt], Ah, wm * 32 + mt * 16, kk, g, tg);
                lda(al[mt], Al, wm * 32 + mt * 16, kk, g, tg);
            }
            #pragma unroll
            for (int nt = 0; nt < 4; nt++) {
                const int nb = wn * 32 + nt * 8;
                u32 bgh2[2], bgl2[2], buh2[2], bul2[2];
                ldb(bgh2, Bgh, nb, kk, g, tg);
                ldb(bgl2, Bgl, nb, kk, g, tg);
                ldb(buh2, Buh, nb, kk, g, tg);
                ldb(bul2, Bul, nb, kk, g, tg);
                #pragma unroll
                for (int mt = 0; mt < 2; mt++) {
                    mma16816(gc[mt][nt], ah[mt], bgh2);
                    mma16816(gc[mt][nt], ah[mt], bgl2);
                    mma16816(gc[mt][nt], al[mt], bgh2);
                    mma16816(uc[mt][nt], ah[mt], buh2);
                    mma16816(uc[mt][nt], ah[mt], bul2);
                    mma16816(uc[mt][nt], al[mt], buh2);
                }
            }
        }
        __syncthreads();
    }

    // epilogue: h = silu(g)*u -> bf16 hi/lo (paired cols tg*2, tg*2+1)
    #pragma unroll
    for (int mt = 0; mt < 2; mt++) {
        #pragma unroll
        for (int half = 0; half < 2; half++) {
            int r = row0 + wm * 32 + mt * 16 + g + half * 8;
            if (r >= cnt) continue;
            size_t rbase = ((size_t)e * CAP + r) * FF + col0 + wn * 32;
            #pragma unroll
            for (int nt = 0; nt < 4; nt++) {
                float g0 = gc[mt][nt][half * 2], g1 = gc[mt][nt][half * 2 + 1];
                float u0 = uc[mt][nt][half * 2], u1 = uc[mt][nt][half * 2 + 1];
                float h0 = (g0 / (1.f + expf(-g0))) * u0;
                float h1 = (g1 / (1.f + expf(-g1))) * u1;
                __nv_bfloat16 h0h = __float2bfloat16(h0);
                __nv_bfloat16 h1h = __float2bfloat16(h1);
                __nv_bfloat16 h0l = __float2bfloat16(h0 - __bfloat162float(h0h));
                __nv_bfloat16 h1l = __float2bfloat16(h1 - __bfloat162float(h1h));
                u32 ph = ((u32)__bfloat16_as_ushort(h1h) << 16) | __bfloat16_as_ushort(h0h);
                u32 pl = ((u32)__bfloat16_as_ushort(h1l) << 16) | __bfloat16_as_ushort(h0l);
                size_t o = rbase + nt * 8 + tg * 2;
                *(u32*)(s_hh + o) = ph;
                *(u32*)(s_hl + o) = pl;
            }
        }
    }
}

// ------------------------------------------------------------------
// GEMM2 (HMMA): y = h * WdT ; out[tok] += w * y
// ------------------------------------------------------------------
__global__ __launch_bounds__(256)
void k_gemm2_mma(float* __restrict__ out) {
    const int e = blockIdx.z;
    int cnt = g_counts[e];
    if (cnt > CAP) cnt = CAP;
    const int row0 = blockIdx.y * 128;
    if (row0 >= cnt) return;
    const int col0 = blockIdx.x * 64;

    extern __shared__ char smem[];
    int*   toks_s = (int*)(smem + SM2_TOK);
    float* wts_s  = (float*)(smem + SM2_WTS);
    __nv_bfloat16* Ah  = (__nv_bfloat16*)(smem + SM2_AH);
    __nv_bfloat16* Al  = (__nv_bfloat16*)(smem + SM2_AL);
    __nv_bfloat16* Bdh = (__nv_bfloat16*)(smem + SM2_BDH);
    __nv_bfloat16* Bdl = (__nv_bfloat16*)(smem + SM2_BDL);

    const int tid = threadIdx.x;
    const int wid = tid >> 5, lane = tid & 31;
    const int g = lane >> 2, tg = lane & 3;
    const int wm = wid & 3, wn = wid >> 2;

    if (tid < 128) {
        int r = row0 + tid;
        toks_s[tid] = (r < cnt) ? g_tok[e * CAP + r] : -1;
        wts_s[tid]  = (r < cnt) ? g_wgt[e * CAP + r] : 0.f;
    }
    __syncthreads();

    const int arow = tid >> 1;
    const int aq = (tid & 1) * 4;
    const bool okA = (row0 + arow < cnt);
    const size_t abase = ((size_t)e * CAP + (okA ? row0 + arow : 0)) * FF;

    float yc[2][4][4] = {};

    for (int c = 0; c < FF / KC; c++) {
        const int k0 = c * KC;
        {
            const uint4* sh = (const uint4*)(s_hh + abase + k0);
            const uint4* sl = (const uint4*)(s_hl + abase + k0);
            const uint4 z = make_uint4(0, 0, 0, 0);
            #pragma unroll
            for (int q = 0; q < 4; q++) {
                int ch = aq + q;
                *(uint4*)(Ah + arow * ASTR + ch * 8) = okA ? sh[ch] : z;
                *(uint4*)(Al + arow * ASTR + ch * 8) = okA ? sl[ch] : z;
            }
        }
        #pragma unroll
        for (int it = 0; it < 4; it++) {
            int idxx = it * 256 + tid;
            int arr = idxx >> 9, rem = idxx & 511;
            int rowb = rem >> 3, ch = rem & 7;
            const __nv_bfloat16* src = (arr == 0) ? s_wdh : s_wdl;
            __nv_bfloat16* dst = (arr == 0) ? Bdh : Bdl;
            uint4 v = ((const uint4*)(src + ((size_t)e * DIM + col0 + rowb) * FF + k0))[ch];
            *(uint4*)(dst + rowb * ASTR + ch * 8) = v;
        }
        __syncthreads();

        #pragma unroll
        for (int ks = 0; ks < KC / 16; ks++) {
            const int kk = ks * 16;
            u32 ah[2][4], al[2][4];
            #pragma unroll
            for (int mt = 0; mt < 2; mt++) {
                lda(ah[mt], Ah, wm * 32 + mt * 16, kk, g, tg);
                lda(al[mt], Al, wm * 32 + mt * 16, kk, g, tg);
            }
            #pragma unroll
            for (int nt = 0; nt < 4; nt++) {
                const int nb = wn * 32 + nt * 8;
                u32 bh2[2], bl2[2];
                ldb(bh2, Bdh, nb, kk, g, tg);
                ldb(bl2, Bdl, nb, kk, g, tg);
                #pragma unroll
                for (int mt = 0; mt < 2; mt++) {
                    mma16816(yc[mt][nt], ah[mt], bh2);
                    mma16816(yc[mt][nt], ah[mt], bl2);
                    mma16816(yc[mt][nt], al[mt], bh2);
                }
            }
        }
        __syncthreads();
    }

    // epilogue: weighted atomic scatter-add
    #pragma unroll
    for (int mt = 0; mt < 2; mt++) {
        #pragma unroll
        for (int half = 0; half < 2; half++) {
            int m = wm * 32 + mt * 16 + g + half * 8;
            int r = row0 + m;
            if (r >= cnt) continue;
            int tok = toks_s[m];
            float wv = wts_s[m];
            float* orow = out + (size_t)tok * DIM + col0 + wn * 32;
            #pragma unroll
            for (int nt = 0; nt < 4; nt++) {
                atomicAdd(&orow[nt * 8 + tg * 2],     wv * yc[mt][nt][half * 2]);
                atomicAdd(&orow[nt * 8 + tg * 2 + 1], wv * yc[mt][nt][half * 2 + 1]);
            }
        }
    }
}

// ------------------------------------------------------------------
extern "C" void kernel_launch(void* const* d_in, const int* in_sizes, int n_in,
                              void* d_out, int out_size) {
    const float* x   = (const float*)d_in[0];   // [T, D] f32
    const int*   idx = (const int*)d_in[1];     // [T, K] int32
    const float* w   = (const float*)d_in[2];   // [T, K] f32
    const float* wg  = (const float*)d_in[3];   // [E, D, F] f32
    const float* wu  = (const float*)d_in[4];   // [E, D, F] f32
    const float* wd  = (const float*)d_in[5];   // [E, F, D] f32
    float* out = (float*)d_out;                 // [T, D] f32

    cudaFuncSetAttribute(k_gemm1_mma, cudaFuncAttributeMaxDynamicSharedMemorySize, SMEM1);
    cudaFuncSetAttribute(k_gemm2_mma, cudaFuncAttributeMaxDynamicSharedMemorySize, SMEM2);

    k_zero<<<512, 256>>>((float4*)out);
    k_dispatch<<<(TKS + 255) / 256, 256>>>(idx, w);
    k_convert_x<<<2048, 256>>>((const float4*)x);
    k_convert_w<<<dim3(FF / 32, DIM / 32, NE), dim3(32, 8)>>>(wg, 0, DIM, FF);
    k_convert_w<<<dim3(FF / 32, DIM / 32, NE), dim3(32, 8)>>>(wu, 1, DIM, FF);
    k_convert_w<<<dim3(DIM / 32, FF / 32, NE), dim3(32, 8)>>>(wd, 2, FF, DIM);
    k_gemm1_mma<<<dim3(FF / 64, CAP / 128, NE), 256, SMEM1>>>();
    k_gemm2_mma<<<dim3(DIM / 64, CAP / 128, NE), 256, SMEM2>>>(out);
}

// round 15
// speedup vs baseline: 1.9199x; 1.0210x over previous
#include <cuda_runtime.h>
#include <cuda_bf16.h>
#include <cstdint>

// Problem constants
#define NE   16
#define KTOP 2
#define DIM  1024
#define FF   512
#define NT   4096
#define CAP  2048
#define TKS  (NT*KTOP)

#define KC   64      // K-chunk staged in smem
#define ASTR 72      // padded row stride (bf16 elems) -> conflict-free frags

typedef unsigned int u32;

// ---- device scratch ----
__device__ int   g_counts[NE];
__device__ int   g_tok[NE*CAP];
__device__ float g_wgt[NE*CAP];

__device__ __nv_bfloat16 s_xh[(size_t)NT*DIM];
__device__ __nv_bfloat16 s_xl[(size_t)NT*DIM];
__device__ __nv_bfloat16 s_wgh[(size_t)NE*FF*DIM];  // WgT [E][F][D]
__device__ __nv_bfloat16 s_wgl[(size_t)NE*FF*DIM];
__device__ __nv_bfloat16 s_wuh[(size_t)NE*FF*DIM];
__device__ __nv_bfloat16 s_wul[(size_t)NE*FF*DIM];
__device__ __nv_bfloat16 s_wdh[(size_t)NE*DIM*FF];  // WdT [E][D][F]
__device__ __nv_bfloat16 s_wdl[(size_t)NE*DIM*FF];
__device__ __nv_bfloat16 s_hh[(size_t)NE*CAP*FF];
__device__ __nv_bfloat16 s_hl[(size_t)NE*CAP*FF];

// ---- mma.sync m16n8k16 bf16 (sm_80+; no 'a'-gated features) ----
__device__ __forceinline__ void mma16816(float* c, const u32* a, const u32* b) {
    asm volatile(
        "mma.sync.aligned.m16n8k16.row.col.f32.bf16.bf16.f32 "
        "{%0,%1,%2,%3}, {%4,%5,%6,%7}, {%8,%9}, {%0,%1,%2,%3};"
        : "+f"(c[0]), "+f"(c[1]), "+f"(c[2]), "+f"(c[3])
        : "r"(a[0]), "r"(a[1]), "r"(a[2]), "r"(a[3]), "r"(b[0]), "r"(b[1]));
}

// A fragment (row-major m16k16)
__device__ __forceinline__ void lda(u32* a, const __nv_bfloat16* As,
                                    int mb, int kk, int g, int tg) {
    const __nv_bfloat16* p = As + (mb + g) * ASTR + kk + tg * 2;
    a[0] = *(const u32*)(p);
    a[1] = *(const u32*)(p + 8 * ASTR);
    a[2] = *(const u32*)(p + 8);
    a[3] = *(const u32*)(p + 8 * ASTR + 8);
}
// B fragment (n8k16, k-contiguous storage)
__device__ __forceinline__ void ldb(u32* b, const __nv_bfloat16* Bs,
                                    int nb, int kk, int g, int tg) {
    const __nv_bfloat16* p = Bs + (nb + g) * ASTR + kk + tg * 2;
    b[0] = *(const u32*)(p);
    b[1] = *(const u32*)(p + 8);
}

// ---- cp.async helpers (sm_80+, compiled clean on compute_103 in R3) ----
__device__ __forceinline__ u32 scvta(const void* p) {
    return (u32)__cvta_generic_to_shared(p);
}
__device__ __forceinline__ void cp16(u32 dst, const void* src) {
    asm volatile("cp.async.cg.shared.global [%0], [%1], 16;"
                 :: "r"(dst), "l"(src));
}
__device__ __forceinline__ void cp16p(u32 dst, const void* src, int bytes) {
    // bytes = 0 -> zero-fill, src not read
    asm volatile("cp.async.cg.shared.global [%0], [%1], 16, %2;"
                 :: "r"(dst), "l"(src), "r"(bytes));
}
__device__ __forceinline__ void cp_commit() {
    asm volatile("cp.async.commit_group;");
}
__device__ __forceinline__ void cp_wait0() {
    asm volatile("cp.async.wait_group 0;");
}

// ------------------------------------------------------------------
__global__ void k_zero(float4* __restrict__ out4) {
    int i = blockIdx.x * blockDim.x + threadIdx.x;
    if (i < NE) g_counts[i] = 0;
    const float4 z = make_float4(0.f, 0.f, 0.f, 0.f);
    for (int j = i; j < NT * DIM / 4; j += gridDim.x * blockDim.x) out4[j] = z;
}

__global__ void k_dispatch(const int* __restrict__ idx,
                           const float* __restrict__ w) {
    int s = blockIdx.x * blockDim.x + threadIdx.x;
    if (s >= TKS) return;
    int e = idx[s];
    if ((unsigned)e >= NE) return;
    int pos = atomicAdd(&g_counts[e], 1);
    if (pos < CAP) {
        g_tok[e * CAP + pos] = s / KTOP;
        g_wgt[e * CAP + pos] = w[s];
    }
}

// X fp32 -> hi/lo bf16
__global__ void k_convert_x(const float4* __restrict__ x4) {
    for (size_t i = blockIdx.x * blockDim.x + threadIdx.x;
         i < (size_t)NT * DIM / 4; i += (size_t)gridDim.x * blockDim.x) {
        float4 v = x4[i];
        __nv_bfloat16 h[4], l[4];
        #pragma unroll
        for (int j = 0; j < 4; j++) {
            float f = (&v.x)[j];
            h[j] = __float2bfloat16(f);
            l[j] = __float2bfloat16(f - __bfloat162float(h[j]));
        }
        *(uint2*)(s_xh + i * 4) = *(const uint2*)h;
        *(uint2*)(s_xl + i * 4) = *(const uint2*)l;
    }
}

// Fused Wg+Wu transpose+split: [E][D][F] fp32 -> [E][F][D] bf16 hi/lo
__global__ void k_convert_wgwu(const float* __restrict__ wg,
                               const float* __restrict__ wu) {
    __shared__ float tg_[32][33], tu_[32][33];
    int e = blockIdx.z;
    int r0 = blockIdx.y * 32, c0 = blockIdx.x * 32;   // r over DIM, c over FF
    const float* sg = wg + (size_t)e * DIM * FF;
    const float* su = wu + (size_t)e * DIM * FF;
    for (int i = threadIdx.y; i < 32; i += 8) {
        size_t o = (size_t)(r0 + i) * FF + c0 + threadIdx.x;
        tg_[i][threadIdx.x] = sg[o];
        tu_[i][threadIdx.x] = su[o];
    }
    __syncthreads();
    for (int i = threadIdx.y; i < 32; i += 8) {
        size_t o = (size_t)e * FF * DIM + (size_t)(c0 + i) * DIM + r0 + threadIdx.x;
        float vg = tg_[threadIdx.x][i];
        float vu = tu_[threadIdx.x][i];
        __nv_bfloat16 gh = __float2bfloat16(vg);
        __nv_bfloat16 uh = __float2bfloat16(vu);
        s_wgh[o] = gh;
        s_wgl[o] = __float2bfloat16(vg - __bfloat162float(gh));
        s_wuh[o] = uh;
        s_wul[o] = __float2bfloat16(vu - __bfloat162float(uh));
    }
}

// Wd transpose+split: [E][F][D] fp32 -> [E][D][F] bf16 hi/lo
__global__ void k_convert_wd(const float* __restrict__ wd) {
    __shared__ float tile[32][33];
    int e = blockIdx.z;
    int r0 = blockIdx.y * 32, c0 = blockIdx.x * 32;   // r over FF, c over DIM
    const float* src = wd + (size_t)e * FF * DIM;
    for (int i = threadIdx.y; i < 32; i += 8)
        tile[i][threadIdx.x] = src[(size_t)(r0 + i) * DIM + c0 + threadIdx.x];
    __syncthreads();
    for (int i = threadIdx.y; i < 32; i += 8) {
        float v = tile[threadIdx.x][i];
        __nv_bfloat16 h = __float2bfloat16(v);
        size_t o = (size_t)e * DIM * FF + (size_t)(c0 + i) * FF + r0 + threadIdx.x;
        s_wdh[o] = h;
        s_wdl[o] = __float2bfloat16(v - __bfloat162float(h));
    }
}

// ---- dynamic smem sizes ----
#define SM1_TOK  0
#define SM1_AH   512
#define SM1_AL   (SM1_AH + 128*ASTR*2)
#define SM1_BGH  (SM1_AL + 128*ASTR*2)
#define SM1_BGL  (SM1_BGH + 64*ASTR*2)
#define SM1_BUH  (SM1_BGL + 64*ASTR*2)
#define SM1_BUL  (SM1_BUH + 64*ASTR*2)
#define SMEM1    (SM1_BUL + 64*ASTR*2)    // 74240

#define SM2_TOK  0
#define SM2_WTS  512
#define SM2_AH   1024
#define SM2_AL   (SM2_AH + 128*ASTR*2)
#define SM2_BDH  (SM2_AL + 128*ASTR*2)
#define SM2_BDL  (SM2_BDH + 64*ASTR*2)
#define SMEM2    (SM2_BDL + 64*ASTR*2)    // 56320

// ------------------------------------------------------------------
// GEMM1 (HMMA): gate = X*WgT, up = X*WuT (bf16 split, fp32 acc);
// h = silu(gate)*up -> bf16 hi/lo. Staging via cp.async.
// ------------------------------------------------------------------
__global__ __launch_bounds__(256)
void k_gemm1_mma() {
    const int e = blockIdx.z;
    int cnt = g_counts[e];
    if (cnt > CAP) cnt = CAP;
    const int row0 = blockIdx.y * 128;
    if (row0 >= cnt) return;
    const int col0 = blockIdx.x * 64;

    extern __shared__ char smem[];
    int* toks_s = (int*)(smem + SM1_TOK);
    __nv_bfloat16* Ah  = (__nv_bfloat16*)(smem + SM1_AH);
    __nv_bfloat16* Al  = (__nv_bfloat16*)(smem + SM1_AL);
    __nv_bfloat16* Bgh = (__nv_bfloat16*)(smem + SM1_BGH);
    __nv_bfloat16* Bgl = (__nv_bfloat16*)(smem + SM1_BGL);
    __nv_bfloat16* Buh = (__nv_bfloat16*)(smem + SM1_BUH);
    __nv_bfloat16* Bul = (__nv_bfloat16*)(smem + SM1_BUL);

    const int tid = threadIdx.x;
    const int wid = tid >> 5, lane = tid & 31;
    const int g = lane >> 2, tg = lane & 3;
    const int wm = wid & 3, wn = wid >> 2;

    if (tid < 128) {
        int r = row0 + tid;
        toks_s[tid] = (r < cnt) ? g_tok[e * CAP + r] : -1;
    }
    __syncthreads();

    const int arow = tid >> 1;
    const int aq = (tid & 1) * 4;
    const int tokA = toks_s[arow];
    const int abytes = (tokA >= 0) ? 16 : 0;
    const __nv_bfloat16* axh = s_xh + (size_t)(tokA < 0 ? 0 : tokA) * DIM;
    const __nv_bfloat16* axl = s_xl + (size_t)(tokA < 0 ? 0 : tokA) * DIM;

    float gc[2][4][4] = {};
    float uc[2][4][4] = {};

    for (int c = 0; c < DIM / KC; c++) {
        const int k0 = c * KC;
        // ---- stage A (gathered token rows), hi & lo, async ----
        #pragma unroll
        for (int q = 0; q < 4; q++) {
            int ch = aq + q;
            cp16p(scvta(Ah + arow * ASTR + ch * 8), axh + k0 + ch * 8, abytes);
            cp16p(scvta(Al + arow * ASTR + ch * 8), axl + k0 + ch * 8, abytes);
        }
        // ---- stage B: 4 arrays x 64 rows x 64 k, async ----
        #pragma unroll
        for (int it = 0; it < 8; it++) {
            int idxx = it * 256 + tid;
            int arr = idxx >> 9, rem = idxx & 511;
            int rowb = rem >> 3, ch = rem & 7;
            const __nv_bfloat16* src =
                (arr == 0) ? s_wgh : (arr == 1) ? s_wgl : (arr == 2) ? s_wuh : s_wul;
            __nv_bfloat16* dst =
                (arr == 0) ? Bgh : (arr == 1) ? Bgl : (arr == 2) ? Buh : Bul;
            cp16(scvta(dst + rowb * ASTR + ch * 8),
                 src + ((size_t)e * FF + col0 + rowb) * DIM + k0 + ch * 8);
        }
        cp_commit();
        cp_wait0();
        __syncthreads();

        #pragma unroll
        for (int ks = 0; ks < KC / 16; ks++) {
            const int kk = ks * 16;
            u32 ah[2][4], al[2][4];
            #pragma unroll
            for (int mt = 0; mt < 2; mt++) {
                lda(ah[mt], Ah, wm * 32 + mt * 16, kk, g, tg);
                lda(al[mt], Al, wm * 32 + mt * 16, kk, g, tg);
            }
            #pragma unroll
            for (int nt = 0; nt < 4; nt++) {
                const int nb = wn * 32 + nt * 8;
                u32 bgh2[2], bgl2[2], buh2[2], bul2[2];
                ldb(bgh2, Bgh, nb, kk, g, tg);
                ldb(bgl2, Bgl, nb, kk, g, tg);
                ldb(buh2, Buh, nb, kk, g, tg);
                ldb(bul2, Bul, nb, kk, g, tg);
                #pragma unroll
                for (int mt = 0; mt < 2; mt++) {
                    mma16816(gc[mt][nt], ah[mt], bgh2);
                    mma16816(gc[mt][nt], ah[mt], bgl2);
                    mma16816(gc[mt][nt], al[mt], bgh2);
                    mma16816(uc[mt][nt], ah[mt], buh2);
                    mma16816(uc[mt][nt], ah[mt], bul2);
                    mma16816(uc[mt][nt], al[mt], buh2);
                }
            }
        }
        __syncthreads();
    }

    // epilogue: h = silu(g)*u -> bf16 hi/lo
    #pragma unroll
    for (int mt = 0; mt < 2; mt++) {
        #pragma unroll
        for (int half = 0; half < 2; half++) {
            int r = row0 + wm * 32 + mt * 16 + g + half * 8;
            if (r >= cnt) continue;
            size_t rbase = ((size_t)e * CAP + r) * FF + col0 + wn * 32;
            #pragma unroll
            for (int nt = 0; nt < 4; nt++) {
                float g0 = gc[mt][nt][half * 2], g1 = gc[mt][nt][half * 2 + 1];
                float u0 = uc[mt][nt][half * 2], u1 = uc[mt][nt][half * 2 + 1];
                float h0 = (g0 / (1.f + expf(-g0))) * u0;
                float h1 = (g1 / (1.f + expf(-g1))) * u1;
                __nv_bfloat16 h0h = __float2bfloat16(h0);
                __nv_bfloat16 h1h = __float2bfloat16(h1);
                __nv_bfloat16 h0l = __float2bfloat16(h0 - __bfloat162float(h0h));
                __nv_bfloat16 h1l = __float2bfloat16(h1 - __bfloat162float(h1h));
                u32 ph = ((u32)__bfloat16_as_ushort(h1h) << 16) | __bfloat16_as_ushort(h0h);
                u32 pl = ((u32)__bfloat16_as_ushort(h1l) << 16) | __bfloat16_as_ushort(h0l);
                size_t o = rbase + nt * 8 + tg * 2;
                *(u32*)(s_hh + o) = ph;
                *(u32*)(s_hl + o) = pl;
            }
        }
    }
}

// ------------------------------------------------------------------
// GEMM2 (HMMA): y = h * WdT ; out[tok] += w * y. Staging via cp.async.
// ------------------------------------------------------------------
__global__ __launch_bounds__(256)
void k_gemm2_mma(float* __restrict__ out) {
    const int e = blockIdx.z;
    int cnt = g_counts[e];
    if (cnt > CAP) cnt = CAP;
    const int row0 = blockIdx.y * 128;
    if (row0 >= cnt) return;
    const int col0 = blockIdx.x * 64;

    extern __shared__ char smem[];
    int*   toks_s = (int*)(smem + SM2_TOK);
    float* wts_s  = (float*)(smem + SM2_WTS);
    __nv_bfloat16* Ah  = (__nv_bfloat16*)(smem + SM2_AH);
    __nv_bfloat16* Al  = (__nv_bfloat16*)(smem + SM2_AL);
    __nv_bfloat16* Bdh = (__nv_bfloat16*)(smem + SM2_BDH);
    __nv_bfloat16* Bdl = (__nv_bfloat16*)(smem + SM2_BDL);

    const int tid = threadIdx.x;
    const int wid = tid >> 5, lane = tid & 31;
    const int g = lane >> 2, tg = lane & 3;
    const int wm = wid & 3, wn = wid >> 2;

    if (tid < 128) {
        int r = row0 + tid;
        toks_s[tid] = (r < cnt) ? g_tok[e * CAP + r] : -1;
        wts_s[tid]  = (r < cnt) ? g_wgt[e * CAP + r] : 0.f;
    }
    __syncthreads();

    const int arow = tid >> 1;
    const int aq = (tid & 1) * 4;
    const bool okA = (row0 + arow < cnt);
    const int abytes = okA ? 16 : 0;
    const size_t abase = ((size_t)e * CAP + (okA ? row0 + arow : 0)) * FF;

    float yc[2][4][4] = {};

    for (int c = 0; c < FF / KC; c++) {
        const int k0 = c * KC;
        #pragma unroll
        for (int q = 0; q < 4; q++) {
            int ch = aq + q;
            cp16p(scvta(Ah + arow * ASTR + ch * 8), s_hh + abase + k0 + ch * 8, abytes);
            cp16p(scvta(Al + arow * ASTR + ch * 8), s_hl + abase + k0 + ch * 8, abytes);
        }
        #pragma unroll
        for (int it = 0; it < 4; it++) {
            int idxx = it * 256 + tid;
            int arr = idxx >> 9, rem = idxx & 511;
            int rowb = rem >> 3, ch = rem & 7;
            const __nv_bfloat16* src = (arr == 0) ? s_wdh : s_wdl;
            __nv_bfloat16* dst = (arr == 0) ? Bdh : Bdl;
            cp16(scvta(dst + rowb * ASTR + ch * 8),
                 src + ((size_t)e * DIM + col0 + rowb) * FF + k0 + ch * 8);
        }
        cp_commit();
        cp_wait0();
        __syncthreads();

        #pragma unroll
        for (int ks = 0; ks < KC / 16; ks++) {
            const int kk = ks * 16;
            u32 ah[2][4], al[2][4];
            #pragma unroll
            for (int mt = 0; mt < 2; mt++) {
                lda(ah[mt], Ah, wm * 32 + mt * 16, kk, g, tg);
                lda(al[mt], Al, wm * 32 + mt * 16, kk, g, tg);
            }
            #pragma unroll
            for (int nt = 0; nt < 4; nt++) {
                const int nb = wn * 32 + nt * 8;
                u32 bh2[2], bl2[2];
                ldb(bh2, Bdh, nb, kk, g, tg);
                ldb(bl2, Bdl, nb, kk, g, tg);
                #pragma unroll
                for (int mt = 0; mt < 2; mt++) {
                    mma16816(yc[mt][nt], ah[mt], bh2);
                    mma16816(yc[mt][nt], ah[mt], bl2);
                    mma16816(yc[mt][nt], al[mt], bh2);
                }
            }
        }
        __syncthreads();
    }

    // epilogue: weighted atomic scatter-add
    #pragma unroll
    for (int mt = 0; mt < 2; mt++) {
        #pragma unroll
        for (int half = 0; half < 2; half++) {
            int m = wm * 32 + mt * 16 + g + half * 8;
            int r = row0 + m;
            if (r >= cnt) continue;
            int tok = toks_s[m];
            float wv = wts_s[m];
            float* orow = out + (size_t)tok * DIM + col0 + wn * 32;
            #pragma unroll
            for (int nt = 0; nt < 4; nt++) {
                atomicAdd(&orow[nt * 8 + tg * 2],     wv * yc[mt][nt][half * 2]);
                atomicAdd(&orow[nt * 8 + tg * 2 + 1], wv * yc[mt][nt][half * 2 + 1]);
            }
        }
    }
}

// ------------------------------------------------------------------
// Launch order matters: gemm1 is launch #6 -> captured by ncu (-s 5 -c 1).
// ------------------------------------------------------------------
extern "C" void kernel_launch(void* const* d_in, const int* in_sizes, int n_in,
                              void* d_out, int out_size) {
    const float* x   = (const float*)d_in[0];   // [T, D] f32
    const int*   idx = (const int*)d_in[1];     // [T, K] int32
    const float* w   = (const float*)d_in[2];   // [T, K] f32
    const float* wg  = (const float*)d_in[3];   // [E, D, F] f32
    const float* wu  = (const float*)d_in[4];   // [E, D, F] f32
    const float* wd  = (const float*)d_in[5];   // [E, F, D] f32
    float* out = (float*)d_out;                 // [T, D] f32

    cudaFuncSetAttribute(k_gemm1_mma, cudaFuncAttributeMaxDynamicSharedMemorySize, SMEM1);
    cudaFuncSetAttribute(k_gemm2_mma, cudaFuncAttributeMaxDynamicSharedMemorySize, SMEM2);

    k_zero<<<512, 256>>>((float4*)out);                                   // 1
    k_dispatch<<<(TKS + 255) / 256, 256>>>(idx, w);                       // 2
    k_convert_x<<<2048, 256>>>((const float4*)x);                         // 3
    k_convert_wgwu<<<dim3(FF / 32, DIM / 32, NE), dim3(32, 8)>>>(wg, wu); // 4
    k_convert_wd<<<dim3(DIM / 32, FF / 32, NE), dim3(32, 8)>>>(wd);       // 5
    k_gemm1_mma<<<dim3(FF / 64, CAP / 128, NE), 256, SMEM1>>>();          // 6 (ncu)
    k_gemm2_mma<<<dim3(DIM / 64, CAP / 128, NE), 256, SMEM2>>>(out);      // 7
}